// round 13
// baseline (speedup 1.0000x reference)
#include <cuda_runtime.h>
#include <cuda_bf16.h>
#include <cstdint>

#define C_  8
#define NQ_ 16
#define NK_ 32
#define B_  128
#define D_  128
#define E_  512
#define H_  8
#define A_  64
#define O_  64

// Scratch (device globals — allocation-free per harness rules).
__device__ float g_query[C_*NQ_*B_*E_];
__device__ float g_key  [C_*NK_*B_*E_];
__device__ float g_value[C_*NK_*B_*E_];

// ===========================================================================
// mma.sync helpers (compile on compute_103 baseline target — no tcgen05)
// ===========================================================================
__device__ __forceinline__ uint32_t smem_u32(const void* p) {
  uint32_t a;
  asm("{ .reg .u64 t; cvta.to.shared.u64 t, %1; cvt.u32.u64 %0, t; }"
      : "=r"(a) : "l"(p));
  return a;
}
__device__ __forceinline__ void ldsm_x4(uint32_t& r0, uint32_t& r1,
                                        uint32_t& r2, uint32_t& r3,
                                        uint32_t addr) {
  asm volatile("ldmatrix.sync.aligned.m8n8.x4.shared.b16 {%0,%1,%2,%3}, [%4];"
               : "=r"(r0), "=r"(r1), "=r"(r2), "=r"(r3) : "r"(addr));
}
__device__ __forceinline__ void mma_bf16(float* d, const uint32_t* a,
                                         uint32_t b0, uint32_t b1) {
  asm volatile(
      "mma.sync.aligned.m16n8k16.row.col.f32.bf16.bf16.f32 "
      "{%0,%1,%2,%3}, {%4,%5,%6,%7}, {%8,%9}, {%0,%1,%2,%3};"
      : "+f"(d[0]), "+f"(d[1]), "+f"(d[2]), "+f"(d[3])
      : "r"(a[0]), "r"(a[1]), "r"(a[2]), "r"(a[3]), "r"(b0), "r"(b1));
}

// smem layout (bytes). Tiles padded to 136 halves/row (272 B):
// 272 mod 128 = 16 -> ldmatrix 8-row fetches hit distinct 16B bank groups.
#define TSTR   136
#define AH_OFF 0
#define AL_OFF 34816          // 128*136*2
#define WH_OFF 69632
#define WL_OFF 87040          // + 64*136*2
#define PROJ_SMEM 104448

// ===========================================================================
// Split-bf16 grouped projection via mma.sync (HMMA).
// grid = (8 n-tiles of 64) x (640 (proj,group)); block 256 thr = 8 warps.
// Block computes Y[g][0:128][n0:n0+64] = (X[g]+PE)(128x128) @ W[g][:,n0:n0+64]
// as Ah*Wh + Ah*Wl + Al*Wh accumulated in fp32 registers (Al*Wl ~2^-18 dropped).
// ===========================================================================
__global__ void __launch_bounds__(256, 2) proj_tc_kernel(
    const float* __restrict__ q, const float* __restrict__ k,
    const float* __restrict__ Wq, const float* __restrict__ Wk,
    const float* __restrict__ Wv,
    float* __restrict__ gq, float* __restrict__ gk, float* __restrict__ gv)
{
  extern __shared__ char sm[];
  __shared__ float pe_s[D_];

  const int tid  = threadIdx.x;
  const int lane = tid & 31;
  const int wid  = tid >> 5;

  // resolve (proj, group)
  const int bid = blockIdx.y;
  const float* Xg; const float* Wg; float* Yg; int slot;
  if (bid < 128) {
    int g = bid;        Xg = q + (size_t)g*(B_*D_); Wg = Wq + (size_t)g*(D_*E_);
    Yg = gq + (size_t)g*(B_*E_); slot = g % NQ_;
  } else if (bid < 384) {
    int g = bid - 128;  Xg = k + (size_t)g*(B_*D_); Wg = Wk + (size_t)g*(D_*E_);
    Yg = gk + (size_t)g*(B_*E_); slot = g % NK_;
  } else {
    int g = bid - 384;  Xg = k + (size_t)g*(B_*D_); Wg = Wv + (size_t)g*(D_*E_);
    Yg = gv + (size_t)g*(B_*E_); slot = g % NK_;
  }
  const int n0 = blockIdx.x * 64;

  __nv_bfloat16* Ah = reinterpret_cast<__nv_bfloat16*>(sm + AH_OFF);
  __nv_bfloat16* Al = reinterpret_cast<__nv_bfloat16*>(sm + AL_OFF);
  __nv_bfloat16* Wh = reinterpret_cast<__nv_bfloat16*>(sm + WH_OFF);
  __nv_bfloat16* Wl = reinterpret_cast<__nv_bfloat16*>(sm + WL_OFF);

  // PE row for this group's slot
  if (tid < D_) {
    const int i = tid >> 1;
    float freq = expf((float)(2*i) * (-9.210340371976184f / (float)D_));
    float ang  = (float)slot * freq;
    pe_s[tid] = (tid & 1) ? cosf(ang) : sinf(ang);
  }
  __syncthreads();

  // convert A = X + PE -> bf16 hi/lo, row-major [m][k], stride 136
  for (int idx = tid; idx < B_*D_; idx += 256) {
    int m = idx >> 7, kk = idx & 127;
    float x = Xg[idx] + pe_s[kk];
    __nv_bfloat16 h = __float2bfloat16(x);
    __nv_bfloat16 l = __float2bfloat16(x - __bfloat162float(h));
    Ah[m*TSTR + kk] = h;
    Al[m*TSTR + kk] = l;
  }
  // convert W n-tile, TRANSPOSED to [n][k] (k contiguous per n), stride 136
  for (int idx = tid; idx < 64*D_; idx += 256) {
    int kk = idx >> 6, n = idx & 63;
    float x = Wg[(size_t)kk*E_ + n0 + n];
    __nv_bfloat16 h = __float2bfloat16(x);
    __nv_bfloat16 l = __float2bfloat16(x - __bfloat162float(h));
    Wh[n*TSTR + kk] = h;
    Wl[n*TSTR + kk] = l;
  }
  __syncthreads();

  // warp tiles: wm in 0..3 -> m0 = wm*32 ; wn in 0..1 -> n base = wn*32
  const int wm = wid & 3;
  const int wn = wid >> 2;

  float acc[2][4][4];
  #pragma unroll
  for (int i = 0; i < 2; ++i)
    #pragma unroll
    for (int j = 0; j < 4; ++j)
      #pragma unroll
      for (int e = 0; e < 4; ++e) acc[i][j][e] = 0.f;

  // per-lane ldmatrix base addresses
  // A (m16k16 frag): lane -> row = (lane&15), col8 = (lane>>4)*8
  const uint32_t a_row  = (uint32_t)(wm*32 + (lane & 15));
  const uint32_t a_col  = (uint32_t)((lane >> 4) << 3);
  uint32_t ah_addr = smem_u32(Ah) + (a_row*TSTR + a_col)*2;
  uint32_t al_addr = smem_u32(Al) + (a_row*TSTR + a_col)*2;
  // B (k16n8 frags, non-trans; smem rows = n, k contiguous):
  // lane -> n = (lane&7) + (lane>=16 ? 8 : 0), k8 = (lane&8)
  const uint32_t b_n = (uint32_t)(wn*32 + (lane & 7) + ((lane >> 4) << 3));
  const uint32_t b_k = (uint32_t)(lane & 8);
  uint32_t wh_addr = smem_u32(Wh) + (b_n*TSTR + b_k)*2;
  uint32_t wl_addr = smem_u32(Wl) + (b_n*TSTR + b_k)*2;

  #pragma unroll 2
  for (int ks = 0; ks < 8; ++ks) {
    const uint32_t ko = (uint32_t)(ks * 32);          // 16 halves
    uint32_t AHf[2][4], ALf[2][4], WHf[2][4], WLf[2][4];
    ldsm_x4(AHf[0][0],AHf[0][1],AHf[0][2],AHf[0][3], ah_addr + ko);
    ldsm_x4(AHf[1][0],AHf[1][1],AHf[1][2],AHf[1][3], ah_addr + 16*TSTR*2 + ko);
    ldsm_x4(ALf[0][0],ALf[0][1],ALf[0][2],ALf[0][3], al_addr + ko);
    ldsm_x4(ALf[1][0],ALf[1][1],ALf[1][2],ALf[1][3], al_addr + 16*TSTR*2 + ko);
    ldsm_x4(WHf[0][0],WHf[0][1],WHf[0][2],WHf[0][3], wh_addr + ko);
    ldsm_x4(WHf[1][0],WHf[1][1],WHf[1][2],WHf[1][3], wh_addr + 16*TSTR*2 + ko);
    ldsm_x4(WLf[0][0],WLf[0][1],WLf[0][2],WLf[0][3], wl_addr + ko);
    ldsm_x4(WLf[1][0],WLf[1][1],WLf[1][2],WLf[1][3], wl_addr + 16*TSTR*2 + ko);

    #pragma unroll
    for (int mf = 0; mf < 2; ++mf) {
      #pragma unroll
      for (int nf2 = 0; nf2 < 2; ++nf2) {
        // frag pair: {b0,b1} = {r0,r1} (n+0..7), {r2,r3} (n+8..15)
        mma_bf16(acc[mf][nf2*2+0], AHf[mf], WHf[nf2][0], WHf[nf2][1]);
        mma_bf16(acc[mf][nf2*2+1], AHf[mf], WHf[nf2][2], WHf[nf2][3]);
        mma_bf16(acc[mf][nf2*2+0], AHf[mf], WLf[nf2][0], WLf[nf2][1]);
        mma_bf16(acc[mf][nf2*2+1], AHf[mf], WLf[nf2][2], WLf[nf2][3]);
        mma_bf16(acc[mf][nf2*2+0], ALf[mf], WHf[nf2][0], WHf[nf2][1]);
        mma_bf16(acc[mf][nf2*2+1], ALf[mf], WHf[nf2][2], WHf[nf2][3]);
      }
    }
  }

  // epilogue: direct fp32 stores (lane l owns rows l/4, l/4+8; cols (l%4)*2)
  const int gm = wm*32;
  const int gn = n0 + wn*32;
  #pragma unroll
  for (int mf = 0; mf < 2; ++mf) {
    #pragma unroll
    for (int nf = 0; nf < 4; ++nf) {
      int row = gm + mf*16 + (lane >> 2);
      int col = gn + nf*8 + (lane & 3)*2;
      *reinterpret_cast<float2*>(Yg + (size_t)row*E_ + col) =
          make_float2(acc[mf][nf][0], acc[mf][nf][1]);
      *reinterpret_cast<float2*>(Yg + (size_t)(row+8)*E_ + col) =
          make_float2(acc[mf][nf][2], acc[mf][nf][3]);
    }
  }
}

// ===========================================================================
// Fused attention (unchanged — control).
// ===========================================================================
__device__ __forceinline__ float warp_max(float x) {
  #pragma unroll
  for (int s = 16; s > 0; s >>= 1)
    x = fmaxf(x, __shfl_xor_sync(0xffffffffu, x, s));
  return x;
}
__device__ __forceinline__ float warp_sum(float x) {
  #pragma unroll
  for (int s = 16; s > 0; s >>= 1)
    x += __shfl_xor_sync(0xffffffffu, x, s);
  return x;
}

__global__ void __launch_bounds__(128) attn_kernel(
    float* __restrict__ Q, const float* __restrict__ K, const float* __restrict__ V)
{
  const int idx = blockIdx.x;
  const int h = idx & (H_-1);
  const int b = (idx >> 3) & (B_-1);
  const int c = idx >> 10;

  __shared__ float Qs[NQ_][64];
  __shared__ float Ks[NK_][65];
  __shared__ float Vs[NK_][65];

  const int tid  = threadIdx.x;
  const int lane = tid & 31;
  const int w    = tid >> 5;

  #pragma unroll
  for (int r = 0; r < 2; ++r) {
    int i = tid + r*128;
    int row = i >> 4;
    int c4  = (i & 15) << 2;
    float4 v = *reinterpret_cast<const float4*>(
        Q + ((size_t)((c*NQ_+row)*B_ + b))*E_ + h*A_ + c4);
    v.x *= 0.125f; v.y *= 0.125f; v.z *= 0.125f; v.w *= 0.125f;
    *reinterpret_cast<float4*>(&Qs[row][c4]) = v;
  }
  #pragma unroll
  for (int r = 0; r < 4; ++r) {
    int i = tid + r*128;
    int row = i >> 4;
    int c4  = (i & 15) << 2;
    size_t off = ((size_t)((c*NK_+row)*B_ + b))*E_ + h*A_ + c4;
    float4 kv = *reinterpret_cast<const float4*>(K + off);
    Ks[row][c4+0]=kv.x; Ks[row][c4+1]=kv.y; Ks[row][c4+2]=kv.z; Ks[row][c4+3]=kv.w;
    float4 vv = *reinterpret_cast<const float4*>(V + off);
    Vs[row][c4+0]=vv.x; Vs[row][c4+1]=vv.y; Vs[row][c4+2]=vv.z; Vs[row][c4+3]=vv.w;
  }
  __syncthreads();

  const int q0 = w * 4;
  float l0 = 0.f, l1 = 0.f, l2 = 0.f, l3 = 0.f;
  #pragma unroll
  for (int a = 0; a < A_; ++a) {
    float kv = Ks[lane][a];
    l0 += Qs[q0+0][a] * kv;
    l1 += Qs[q0+1][a] * kv;
    l2 += Qs[q0+2][a] * kv;
    l3 += Qs[q0+3][a] * kv;
  }

  float p0, p1, p2, p3;
  {
    float m0 = warp_max(l0), m1 = warp_max(l1), m2 = warp_max(l2), m3 = warp_max(l3);
    p0 = __expf(l0 - m0); p1 = __expf(l1 - m1);
    p2 = __expf(l2 - m2); p3 = __expf(l3 - m3);
    float s0 = warp_sum(p0), s1 = warp_sum(p1), s2 = warp_sum(p2), s3 = warp_sum(p3);
    p0 *= 1.f/s0; p1 *= 1.f/s1; p2 *= 1.f/s2; p3 *= 1.f/s3;
  }

  float a00=0.f,a01=0.f,a10=0.f,a11=0.f,a20=0.f,a21=0.f,a30=0.f,a31=0.f;
  #pragma unroll
  for (int kk = 0; kk < NK_; ++kk) {
    float v0 = Vs[kk][lane];
    float v1 = Vs[kk][lane+32];
    float pa = __shfl_sync(0xffffffffu, p0, kk);
    a00 += pa*v0; a01 += pa*v1;
    float pb = __shfl_sync(0xffffffffu, p1, kk);
    a10 += pb*v0; a11 += pb*v1;
    float pc = __shfl_sync(0xffffffffu, p2, kk);
    a20 += pc*v0; a21 += pc*v1;
    float pd = __shfl_sync(0xffffffffu, p3, kk);
    a30 += pd*v0; a31 += pd*v1;
  }

  {
    float* dst0 = Q + ((size_t)((c*NQ_+q0+0)*B_ + b))*E_ + h*A_;
    float* dst1 = Q + ((size_t)((c*NQ_+q0+1)*B_ + b))*E_ + h*A_;
    float* dst2 = Q + ((size_t)((c*NQ_+q0+2)*B_ + b))*E_ + h*A_;
    float* dst3 = Q + ((size_t)((c*NQ_+q0+3)*B_ + b))*E_ + h*A_;
    dst0[lane] = a00; dst0[lane+32] = a01;
    dst1[lane] = a10; dst1[lane+32] = a11;
    dst2[lane] = a20; dst2[lane+32] = a21;
    dst3[lane] = a30; dst3[lane+32] = a31;
  }
}

// ===========================================================================
// Output projection (unchanged — control).
// ===========================================================================
__global__ void __launch_bounds__(256) outproj_kernel(
    const float* __restrict__ Xa, const float* __restrict__ Wp,
    float* __restrict__ Y)
{
  const int g = blockIdx.x;
  const float* Ag = Xa + (size_t)g * (B_*E_);
  const float* Wg = Wp + (size_t)g * (E_*O_);
  float*       Yg = Y  + (size_t)g * (B_*O_);

  __shared__ float As[16][132];
  __shared__ float Bs[16][64];

  const int tid = threadIdx.x;
  const int tx = tid & 15;
  const int ty = tid >> 4;

  float acc[8][4];
  #pragma unroll
  for (int i = 0; i < 8; ++i)
    #pragma unroll
    for (int j = 0; j < 4; ++j) acc[i][j] = 0.f;

  for (int k0 = 0; k0 < E_; k0 += 16) {
    #pragma unroll
    for (int r = 0; r < 2; ++r) {
      int idx = tid + r*256;
      int row = idx >> 2;
      int c4  = (idx & 3) << 2;
      float4 v = *reinterpret_cast<const float4*>(Ag + (size_t)row*E_ + k0 + c4);
      As[c4+0][row]=v.x; As[c4+1][row]=v.y; As[c4+2][row]=v.z; As[c4+3][row]=v.w;
    }
    {
      int row = tid >> 4;
      int c4  = (tid & 15) << 2;
      *reinterpret_cast<float4*>(&Bs[row][c4]) =
          *reinterpret_cast<const float4*>(Wg + (size_t)(k0+row)*O_ + c4);
    }
    __syncthreads();

    #pragma unroll
    for (int kk = 0; kk < 16; ++kk) {
      float a[8], bb[4];
      #pragma unroll
      for (int i = 0; i < 8; ++i) a[i]  = As[kk][ty*8+i];
      #pragma unroll
      for (int j = 0; j < 4; ++j) bb[j] = Bs[kk][tx*4+j];
      #pragma unroll
      for (int i = 0; i < 8; ++i)
        #pragma unroll
        for (int j = 0; j < 4; ++j) acc[i][j] += a[i]*bb[j];
    }
    __syncthreads();
  }

  #pragma unroll
  for (int i = 0; i < 8; ++i) {
    int m = ty*8 + i;
    *reinterpret_cast<float4*>(Yg + (size_t)m*O_ + tx*4) =
        make_float4(acc[i][0], acc[i][1], acc[i][2], acc[i][3]);
  }
}

extern "C" void kernel_launch(void* const* d_in, const int* in_sizes, int n_in,
                              void* d_out, int out_size)
{
  const float* q  = (const float*)d_in[0];
  const float* k  = (const float*)d_in[1];
  const float* Wq = (const float*)d_in[2];
  const float* Wk = (const float*)d_in[3];
  const float* Wv = (const float*)d_in[4];
  const float* Wp = (const float*)d_in[5];
  float* out = (float*)d_out;

  float *gq, *gk, *gv;
  cudaGetSymbolAddress((void**)&gq, g_query);
  cudaGetSymbolAddress((void**)&gk, g_key);
  cudaGetSymbolAddress((void**)&gv, g_value);

  cudaFuncSetAttribute(proj_tc_kernel,
                       cudaFuncAttributeMaxDynamicSharedMemorySize, PROJ_SMEM);

  proj_tc_kernel<<<dim3(8, 640), 256, PROJ_SMEM>>>(q, k, Wq, Wk, Wv, gq, gk, gv);
  attn_kernel<<<C_*B_*H_, 128>>>(gq, gk, gv);
  outproj_kernel<<<C_*NQ_, 256>>>(gq, Wp, out);
}

// round 17
// speedup vs baseline: 1.3080x; 1.3080x over previous
#include <cuda_runtime.h>
#include <cuda_bf16.h>
#include <cstdint>

#define C_  8
#define NQ_ 16
#define NK_ 32
#define B_  128
#define D_  128
#define E_  512
#define H_  8
#define A_  64
#define O_  64

// Scratch (device globals — allocation-free per harness rules).
__device__ float g_query[C_*NQ_*B_*E_];
__device__ float g_key  [C_*NK_*B_*E_];
__device__ float g_value[C_*NK_*B_*E_];
// Pre-converted bf16 hi/lo activations (q+PE, k+PE). 24 MB total -> L2-resident.
__device__ __nv_bfloat16 g_aqh[C_*NQ_*B_*D_];
__device__ __nv_bfloat16 g_aql[C_*NQ_*B_*D_];
__device__ __nv_bfloat16 g_akh[C_*NK_*B_*D_];
__device__ __nv_bfloat16 g_akl[C_*NK_*B_*D_];

// ===========================================================================
// helpers (compile on compute_103 baseline target — no tcgen05)
// ===========================================================================
__device__ __forceinline__ uint32_t smem_u32(const void* p) {
  uint32_t a;
  asm("{ .reg .u64 t; cvta.to.shared.u64 t, %1; cvt.u32.u64 %0, t; }"
      : "=r"(a) : "l"(p));
  return a;
}
__device__ __forceinline__ void ldsm_x4(uint32_t& r0, uint32_t& r1,
                                        uint32_t& r2, uint32_t& r3,
                                        uint32_t addr) {
  asm volatile("ldmatrix.sync.aligned.m8n8.x4.shared.b16 {%0,%1,%2,%3}, [%4];"
               : "=r"(r0), "=r"(r1), "=r"(r2), "=r"(r3) : "r"(addr));
}
__device__ __forceinline__ void mma_bf16(float* d, const uint32_t* a,
                                         uint32_t b0, uint32_t b1) {
  asm volatile(
      "mma.sync.aligned.m16n8k16.row.col.f32.bf16.bf16.f32 "
      "{%0,%1,%2,%3}, {%4,%5,%6,%7}, {%8,%9}, {%0,%1,%2,%3};"
      : "+f"(d[0]), "+f"(d[1]), "+f"(d[2]), "+f"(d[3])
      : "r"(a[0]), "r"(a[1]), "r"(a[2]), "r"(a[3]), "r"(b0), "r"(b1));
}
__device__ __forceinline__ void cp16(uint32_t dst, const void* src) {
  asm volatile("cp.async.cg.shared.global [%0], [%1], 16;"
               :: "r"(dst), "l"(src));
}

// smem layout (bytes). Tiles padded to 136 halves/row (272 B):
// 272 mod 128 = 16 -> ldmatrix 8-row fetches hit distinct 16B bank groups.
#define TSTR   136
#define AH_OFF 0
#define AL_OFF 34816          // 128*136*2
#define WH_OFF 69632
#define WL_OFF 87040          // + 64*136*2
#define PROJ_SMEM 104448

// ===========================================================================
// PE + bf16 hi/lo pre-conversion of activations.
// grid = 384 blocks: [0,128) q slices (slot = s % NQ), [128,384) k slices.
// One block per (c, n) slice of B*D = 16384 floats.
// ===========================================================================
__global__ void __launch_bounds__(256) convert_a_kernel(
    const float* __restrict__ q, const float* __restrict__ k,
    __nv_bfloat16* __restrict__ aqh, __nv_bfloat16* __restrict__ aql,
    __nv_bfloat16* __restrict__ akh, __nv_bfloat16* __restrict__ akl)
{
  __shared__ float pe_s[D_];
  const int tid = threadIdx.x;
  const int blk = blockIdx.x;

  const float* src; __nv_bfloat16 *dh, *dl; int slot;
  if (blk < 128) {
    slot = blk % NQ_;
    src = q + (size_t)blk*(B_*D_);
    dh = aqh + (size_t)blk*(B_*D_);  dl = aql + (size_t)blk*(B_*D_);
  } else {
    int s = blk - 128;
    slot = s % NK_;
    src = k + (size_t)s*(B_*D_);
    dh = akh + (size_t)s*(B_*D_);    dl = akl + (size_t)s*(B_*D_);
  }

  if (tid < D_) {
    const int i = tid >> 1;
    float freq = expf((float)(2*i) * (-9.210340371976184f / (float)D_));
    float ang  = (float)slot * freq;
    pe_s[tid] = (tid & 1) ? cosf(ang) : sinf(ang);
  }
  __syncthreads();

  for (int i = tid; i < (B_*D_)/4; i += 256) {
    float4 v = reinterpret_cast<const float4*>(src)[i];
    int d = (i & ((D_/4)-1)) * 4;
    v.x += pe_s[d+0]; v.y += pe_s[d+1]; v.z += pe_s[d+2]; v.w += pe_s[d+3];
    __nv_bfloat16 h0 = __float2bfloat16(v.x), h1 = __float2bfloat16(v.y);
    __nv_bfloat16 h2 = __float2bfloat16(v.z), h3 = __float2bfloat16(v.w);
    __nv_bfloat162 hh0; hh0.x = h0; hh0.y = h1;
    __nv_bfloat162 hh1; hh1.x = h2; hh1.y = h3;
    __nv_bfloat162 ll0, ll1;
    ll0.x = __float2bfloat16(v.x - __bfloat162float(h0));
    ll0.y = __float2bfloat16(v.y - __bfloat162float(h1));
    ll1.x = __float2bfloat16(v.z - __bfloat162float(h2));
    ll1.y = __float2bfloat16(v.w - __bfloat162float(h3));
    reinterpret_cast<__nv_bfloat162*>(dh)[i*2+0] = hh0;
    reinterpret_cast<__nv_bfloat162*>(dh)[i*2+1] = hh1;
    reinterpret_cast<__nv_bfloat162*>(dl)[i*2+0] = ll0;
    reinterpret_cast<__nv_bfloat162*>(dl)[i*2+1] = ll1;
  }
}

// ===========================================================================
// Split-bf16 grouped projection via mma.sync (HMMA).
// grid = (8 n-tiles of 64) x (640 (proj,group)); block 256 thr = 8 warps.
// A tiles arrive pre-converted (cp.async bf16, L2-resident); W converted
// in-kernel (each W element used exactly once chip-wide).
// 3-pass split: Ah*Wh + Ah*Wl + Al*Wh (Al*Wl ~2^-18 dropped).
// ===========================================================================
__global__ void __launch_bounds__(256, 2) proj_tc_kernel(
    const __nv_bfloat16* __restrict__ aqh, const __nv_bfloat16* __restrict__ aql,
    const __nv_bfloat16* __restrict__ akh, const __nv_bfloat16* __restrict__ akl,
    const float* __restrict__ Wq, const float* __restrict__ Wk,
    const float* __restrict__ Wv,
    float* __restrict__ gq, float* __restrict__ gk, float* __restrict__ gv)
{
  extern __shared__ char sm[];

  const int tid  = threadIdx.x;
  const int lane = tid & 31;
  const int wid  = tid >> 5;

  // resolve (proj, group)
  const int bid = blockIdx.y;
  const __nv_bfloat16 *Agh, *Agl; const float* Wg; float* Yg;
  if (bid < 128) {
    int g = bid;
    Agh = aqh + (size_t)g*(B_*D_); Agl = aql + (size_t)g*(B_*D_);
    Wg = Wq + (size_t)g*(D_*E_);   Yg = gq + (size_t)g*(B_*E_);
  } else if (bid < 384) {
    int g = bid - 128;
    Agh = akh + (size_t)g*(B_*D_); Agl = akl + (size_t)g*(B_*D_);
    Wg = Wk + (size_t)g*(D_*E_);   Yg = gk + (size_t)g*(B_*E_);
  } else {
    int g = bid - 384;
    Agh = akh + (size_t)g*(B_*D_); Agl = akl + (size_t)g*(B_*D_);
    Wg = Wv + (size_t)g*(D_*E_);   Yg = gv + (size_t)g*(B_*E_);
  }
  const int n0 = blockIdx.x * 64;

  __nv_bfloat16* Ah = reinterpret_cast<__nv_bfloat16*>(sm + AH_OFF);
  __nv_bfloat16* Al = reinterpret_cast<__nv_bfloat16*>(sm + AL_OFF);
  __nv_bfloat16* Wh = reinterpret_cast<__nv_bfloat16*>(sm + WH_OFF);
  __nv_bfloat16* Wl = reinterpret_cast<__nv_bfloat16*>(sm + WL_OFF);
  const uint32_t ah_s = smem_u32(Ah), al_s = smem_u32(Al);

  // ---- A tiles: async bf16 copies (overlap with W convert below) ----
  // 128 rows x 256B per matrix = 2048 16B-chunks; 8 per thread per matrix.
  #pragma unroll
  for (int r = 0; r < 8; ++r) {
    int ch  = tid + r*256;
    int row = ch >> 4;
    int c16 = ch & 15;                    // 16B unit within row (8 halves)
    uint32_t doff = (uint32_t)(row*TSTR + c16*8) * 2;
    size_t   soff = (size_t)(row*D_ + c16*8);
    cp16(ah_s + doff, Agh + soff);
    cp16(al_s + doff, Agl + soff);
  }
  asm volatile("cp.async.commit_group;" ::: "memory");

  // ---- W n-tile convert (transpose to [n][k], k contiguous), stride 136 ----
  for (int idx = tid; idx < 64*D_; idx += 256) {
    int kk = idx >> 6, n = idx & 63;
    float x = Wg[(size_t)kk*E_ + n0 + n];
    __nv_bfloat16 h = __float2bfloat16(x);
    __nv_bfloat16 l = __float2bfloat16(x - __bfloat162float(h));
    Wh[n*TSTR + kk] = h;
    Wl[n*TSTR + kk] = l;
  }
  asm volatile("cp.async.wait_group 0;" ::: "memory");
  __syncthreads();

  // warp tiles: wm in 0..3 -> m0 = wm*32 ; wn in 0..1 -> n base = wn*32
  const int wm = wid & 3;
  const int wn = wid >> 2;

  float acc[2][4][4];
  #pragma unroll
  for (int i = 0; i < 2; ++i)
    #pragma unroll
    for (int j = 0; j < 4; ++j)
      #pragma unroll
      for (int e = 0; e < 4; ++e) acc[i][j][e] = 0.f;

  // per-lane ldmatrix base addresses
  const uint32_t a_row  = (uint32_t)(wm*32 + (lane & 15));
  const uint32_t a_col  = (uint32_t)((lane >> 4) << 3);
  uint32_t ah_addr = ah_s + (a_row*TSTR + a_col)*2;
  uint32_t al_addr = al_s + (a_row*TSTR + a_col)*2;
  const uint32_t b_n = (uint32_t)(wn*32 + (lane & 7) + ((lane >> 4) << 3));
  const uint32_t b_k = (uint32_t)(lane & 8);
  uint32_t wh_addr = smem_u32(Wh) + (b_n*TSTR + b_k)*2;
  uint32_t wl_addr = smem_u32(Wl) + (b_n*TSTR + b_k)*2;

  #pragma unroll 2
  for (int ks = 0; ks < 8; ++ks) {
    const uint32_t ko = (uint32_t)(ks * 32);          // 16 halves
    uint32_t AHf[2][4], ALf[2][4], WHf[2][4], WLf[2][4];
    ldsm_x4(AHf[0][0],AHf[0][1],AHf[0][2],AHf[0][3], ah_addr + ko);
    ldsm_x4(AHf[1][0],AHf[1][1],AHf[1][2],AHf[1][3], ah_addr + 16*TSTR*2 + ko);
    ldsm_x4(ALf[0][0],ALf[0][1],ALf[0][2],ALf[0][3], al_addr + ko);
    ldsm_x4(ALf[1][0],ALf[1][1],ALf[1][2],ALf[1][3], al_addr + 16*TSTR*2 + ko);
    ldsm_x4(WHf[0][0],WHf[0][1],WHf[0][2],WHf[0][3], wh_addr + ko);
    ldsm_x4(WHf[1][0],WHf[1][1],WHf[1][2],WHf[1][3], wh_addr + 16*TSTR*2 + ko);
    ldsm_x4(WLf[0][0],WLf[0][1],WLf[0][2],WLf[0][3], wl_addr + ko);
    ldsm_x4(WLf[1][0],WLf[1][1],WLf[1][2],WLf[1][3], wl_addr + 16*TSTR*2 + ko);

    #pragma unroll
    for (int mf = 0; mf < 2; ++mf) {
      #pragma unroll
      for (int nf2 = 0; nf2 < 2; ++nf2) {
        mma_bf16(acc[mf][nf2*2+0], AHf[mf], WHf[nf2][0], WHf[nf2][1]);
        mma_bf16(acc[mf][nf2*2+1], AHf[mf], WHf[nf2][2], WHf[nf2][3]);
        mma_bf16(acc[mf][nf2*2+0], AHf[mf], WLf[nf2][0], WLf[nf2][1]);
        mma_bf16(acc[mf][nf2*2+1], AHf[mf], WLf[nf2][2], WLf[nf2][3]);
        mma_bf16(acc[mf][nf2*2+0], ALf[mf], WHf[nf2][0], WHf[nf2][1]);
        mma_bf16(acc[mf][nf2*2+1], ALf[mf], WHf[nf2][2], WHf[nf2][3]);
      }
    }
  }

  // epilogue: direct fp32 stores
  const int gm = wm*32;
  const int gn = n0 + wn*32;
  #pragma unroll
  for (int mf = 0; mf < 2; ++mf) {
    #pragma unroll
    for (int nf = 0; nf < 4; ++nf) {
      int row = gm + mf*16 + (lane >> 2);
      int col = gn + nf*8 + (lane & 3)*2;
      *reinterpret_cast<float2*>(Yg + (size_t)row*E_ + col) =
          make_float2(acc[mf][nf][0], acc[mf][nf][1]);
      *reinterpret_cast<float2*>(Yg + (size_t)(row+8)*E_ + col) =
          make_float2(acc[mf][nf][2], acc[mf][nf][3]);
    }
  }
}

// ===========================================================================
// Fused attention (unchanged — control).
// ===========================================================================
__device__ __forceinline__ float warp_max(float x) {
  #pragma unroll
  for (int s = 16; s > 0; s >>= 1)
    x = fmaxf(x, __shfl_xor_sync(0xffffffffu, x, s));
  return x;
}
__device__ __forceinline__ float warp_sum(float x) {
  #pragma unroll
  for (int s = 16; s > 0; s >>= 1)
    x += __shfl_xor_sync(0xffffffffu, x, s);
  return x;
}

__global__ void __launch_bounds__(128) attn_kernel(
    float* __restrict__ Q, const float* __restrict__ K, const float* __restrict__ V)
{
  const int idx = blockIdx.x;
  const int h = idx & (H_-1);
  const int b = (idx >> 3) & (B_-1);
  const int c = idx >> 10;

  __shared__ float Qs[NQ_][64];
  __shared__ float Ks[NK_][65];
  __shared__ float Vs[NK_][65];

  const int tid  = threadIdx.x;
  const int lane = tid & 31;
  const int w    = tid >> 5;

  #pragma unroll
  for (int r = 0; r < 2; ++r) {
    int i = tid + r*128;
    int row = i >> 4;
    int c4  = (i & 15) << 2;
    float4 v = *reinterpret_cast<const float4*>(
        Q + ((size_t)((c*NQ_+row)*B_ + b))*E_ + h*A_ + c4);
    v.x *= 0.125f; v.y *= 0.125f; v.z *= 0.125f; v.w *= 0.125f;
    *reinterpret_cast<float4*>(&Qs[row][c4]) = v;
  }
  #pragma unroll
  for (int r = 0; r < 4; ++r) {
    int i = tid + r*128;
    int row = i >> 4;
    int c4  = (i & 15) << 2;
    size_t off = ((size_t)((c*NK_+row)*B_ + b))*E_ + h*A_ + c4;
    float4 kv = *reinterpret_cast<const float4*>(K + off);
    Ks[row][c4+0]=kv.x; Ks[row][c4+1]=kv.y; Ks[row][c4+2]=kv.z; Ks[row][c4+3]=kv.w;
    float4 vv = *reinterpret_cast<const float4*>(V + off);
    Vs[row][c4+0]=vv.x; Vs[row][c4+1]=vv.y; Vs[row][c4+2]=vv.z; Vs[row][c4+3]=vv.w;
  }
  __syncthreads();

  const int q0 = w * 4;
  float l0 = 0.f, l1 = 0.f, l2 = 0.f, l3 = 0.f;
  #pragma unroll
  for (int a = 0; a < A_; ++a) {
    float kv = Ks[lane][a];
    l0 += Qs[q0+0][a] * kv;
    l1 += Qs[q0+1][a] * kv;
    l2 += Qs[q0+2][a] * kv;
    l3 += Qs[q0+3][a] * kv;
  }

  float p0, p1, p2, p3;
  {
    float m0 = warp_max(l0), m1 = warp_max(l1), m2 = warp_max(l2), m3 = warp_max(l3);
    p0 = __expf(l0 - m0); p1 = __expf(l1 - m1);
    p2 = __expf(l2 - m2); p3 = __expf(l3 - m3);
    float s0 = warp_sum(p0), s1 = warp_sum(p1), s2 = warp_sum(p2), s3 = warp_sum(p3);
    p0 *= 1.f/s0; p1 *= 1.f/s1; p2 *= 1.f/s2; p3 *= 1.f/s3;
  }

  float a00=0.f,a01=0.f,a10=0.f,a11=0.f,a20=0.f,a21=0.f,a30=0.f,a31=0.f;
  #pragma unroll
  for (int kk = 0; kk < NK_; ++kk) {
    float v0 = Vs[kk][lane];
    float v1 = Vs[kk][lane+32];
    float pa = __shfl_sync(0xffffffffu, p0, kk);
    a00 += pa*v0; a01 += pa*v1;
    float pb = __shfl_sync(0xffffffffu, p1, kk);
    a10 += pb*v0; a11 += pb*v1;
    float pc = __shfl_sync(0xffffffffu, p2, kk);
    a20 += pc*v0; a21 += pc*v1;
    float pd = __shfl_sync(0xffffffffu, p3, kk);
    a30 += pd*v0; a31 += pd*v1;
  }

  {
    float* dst0 = Q + ((size_t)((c*NQ_+q0+0)*B_ + b))*E_ + h*A_;
    float* dst1 = Q + ((size_t)((c*NQ_+q0+1)*B_ + b))*E_ + h*A_;
    float* dst2 = Q + ((size_t)((c*NQ_+q0+2)*B_ + b))*E_ + h*A_;
    float* dst3 = Q + ((size_t)((c*NQ_+q0+3)*B_ + b))*E_ + h*A_;
    dst0[lane] = a00; dst0[lane+32] = a01;
    dst1[lane] = a10; dst1[lane+32] = a11;
    dst2[lane] = a20; dst2[lane+32] = a21;
    dst3[lane] = a30; dst3[lane+32] = a31;
  }
}

// ===========================================================================
// Output projection (unchanged — control).
// ===========================================================================
__global__ void __launch_bounds__(256) outproj_kernel(
    const float* __restrict__ Xa, const float* __restrict__ Wp,
    float* __restrict__ Y)
{
  const int g = blockIdx.x;
  const float* Ag = Xa + (size_t)g * (B_*E_);
  const float* Wg = Wp + (size_t)g * (E_*O_);
  float*       Yg = Y  + (size_t)g * (B_*O_);

  __shared__ float As[16][132];
  __shared__ float Bs[16][64];

  const int tid = threadIdx.x;
  const int tx = tid & 15;
  const int ty = tid >> 4;

  float acc[8][4];
  #pragma unroll
  for (int i = 0; i < 8; ++i)
    #pragma unroll
    for (int j = 0; j < 4; ++j) acc[i][j] = 0.f;

  for (int k0 = 0; k0 < E_; k0 += 16) {
    #pragma unroll
    for (int r = 0; r < 2; ++r) {
      int idx = tid + r*256;
      int row = idx >> 2;
      int c4  = (idx & 3) << 2;
      float4 v = *reinterpret_cast<const float4*>(Ag + (size_t)row*E_ + k0 + c4);
      As[c4+0][row]=v.x; As[c4+1][row]=v.y; As[c4+2][row]=v.z; As[c4+3][row]=v.w;
    }
    {
      int row = tid >> 4;
      int c4  = (tid & 15) << 2;
      *reinterpret_cast<float4*>(&Bs[row][c4]) =
          *reinterpret_cast<const float4*>(Wg + (size_t)(k0+row)*O_ + c4);
    }
    __syncthreads();

    #pragma unroll
    for (int kk = 0; kk < 16; ++kk) {
      float a[8], bb[4];
      #pragma unroll
      for (int i = 0; i < 8; ++i) a[i]  = As[kk][ty*8+i];
      #pragma unroll
      for (int j = 0; j < 4; ++j) bb[j] = Bs[kk][tx*4+j];
      #pragma unroll
      for (int i = 0; i < 8; ++i)
        #pragma unroll
        for (int j = 0; j < 4; ++j) acc[i][j] += a[i]*bb[j];
    }
    __syncthreads();
  }

  #pragma unroll
  for (int i = 0; i < 8; ++i) {
    int m = ty*8 + i;
    *reinterpret_cast<float4*>(Yg + (size_t)m*O_ + tx*4) =
        make_float4(acc[i][0], acc[i][1], acc[i][2], acc[i][3]);
  }
}

extern "C" void kernel_launch(void* const* d_in, const int* in_sizes, int n_in,
                              void* d_out, int out_size)
{
  const float* q  = (const float*)d_in[0];
  const float* k  = (const float*)d_in[1];
  const float* Wq = (const float*)d_in[2];
  const float* Wk = (const float*)d_in[3];
  const float* Wv = (const float*)d_in[4];
  const float* Wp = (const float*)d_in[5];
  float* out = (float*)d_out;

  float *gq, *gk, *gv;
  __nv_bfloat16 *aqh, *aql, *akh, *akl;
  cudaGetSymbolAddress((void**)&gq, g_query);
  cudaGetSymbolAddress((void**)&gk, g_key);
  cudaGetSymbolAddress((void**)&gv, g_value);
  cudaGetSymbolAddress((void**)&aqh, g_aqh);
  cudaGetSymbolAddress((void**)&aql, g_aql);
  cudaGetSymbolAddress((void**)&akh, g_akh);
  cudaGetSymbolAddress((void**)&akl, g_akl);

  cudaFuncSetAttribute(proj_tc_kernel,
                       cudaFuncAttributeMaxDynamicSharedMemorySize, PROJ_SMEM);

  convert_a_kernel<<<384, 256>>>(q, k, aqh, aql, akh, akl);
  proj_tc_kernel<<<dim3(8, 640), 256, PROJ_SMEM>>>(aqh, aql, akh, akl,
                                                   Wq, Wk, Wv, gq, gk, gv);
  attn_kernel<<<C_*B_*H_, 128>>>(gq, gk, gv);
  outproj_kernel<<<C_*NQ_, 256>>>(gq, Wp, out);
}